// round 3
// baseline (speedup 1.0000x reference)
#include <cuda_runtime.h>
#include <cuda_bf16.h>
#include <cstdint>

// ---------------------------------------------------------------------------
// ConvTranspose4d: x[4,64,12,12,12,12] (*) w[64,64,3,3,3,3], stride 2, +bias
// out[4,64,25,25,25,25] fp32.
//
// Strategy: gather formulation. Per output dim: even o -> k in {0,2},
// odd o -> k = {1}. One block per (b, o1, o2, same-parity o3-pair).
// Loop over valid (k1,k2,k3) combos; stage weight slice [ci][k4][co] (48KB)
// and input slice [ci][i4][s] (6.5KB) in shared; register-tile
// 4co x 2o3 x <=4 o4 per thread. Warps are o4-parity-pure (no divergence),
// parity swizzled per wave to balance FFMA load across SMSPs.
// ---------------------------------------------------------------------------

#define CI 64
#define CO 64
#define LI 12
#define LO 25
#define XCI 20736            // 12^4
#define WSLICE 12288         // 64ci * 3k4 * 64co
#define OSTR_C 390625        // 25^4

__device__ float g_wt[27 * WSLICE];   // [k123][ci][k4][co], 1.33 MB scratch

// --- weight pre-transpose: w[ci][co][k1][k2][k3][k4] -> wt[k123][ci][k4][co]
__global__ void wtrans_kernel(const float* __restrict__ w) {
    int t = blockIdx.x * 256 + threadIdx.x;
    if (t >= 27 * WSLICE) return;
    int co   = t & 63;
    int k4   = (t >> 6) % 3;
    int ci   = (t / 192) & 63;
    int k123 = t / WSLICE;
    g_wt[t] = w[(size_t)(ci * 64 + co) * 81 + k123 * 3 + k4];
}

__device__ __forceinline__ void taps(int o, int& n, int* kl, int* il) {
    if (o & 1) { n = 1; kl[0] = 1; il[0] = (o - 1) >> 1; }
    else {
        n = 0; int ih = o >> 1;
        if (ih < LI)  { kl[n] = 0; il[n] = ih;     n++; }
        if (ih >= 1)  { kl[n] = 2; il[n] = ih - 1; n++; }
    }
}

// Inner product loop. P = o4 parity (warp uniform). JN = #o4 register columns.
template <int P, int JN>
__device__ __forceinline__ void inner_loop(const float* __restrict__ ws,
                                           const float2* __restrict__ xs2,
                                           int co_base,
                                           const int i4a[4], const int i4b[4],
                                           float (&acc)[2][4][4]) {
#pragma unroll 2
    for (int ci = 0; ci < CI; ++ci) {
        const float4 wa = *(const float4*)(ws + (ci * 3 + P) * 64 + co_base);
#pragma unroll
        for (int j = 0; j < JN; ++j) {
            float2 xv = xs2[ci * 13 + i4a[j]];
            acc[0][j][0] = fmaf(wa.x, xv.x, acc[0][j][0]);
            acc[0][j][1] = fmaf(wa.y, xv.x, acc[0][j][1]);
            acc[0][j][2] = fmaf(wa.z, xv.x, acc[0][j][2]);
            acc[0][j][3] = fmaf(wa.w, xv.x, acc[0][j][3]);
            acc[1][j][0] = fmaf(wa.x, xv.y, acc[1][j][0]);
            acc[1][j][1] = fmaf(wa.y, xv.y, acc[1][j][1]);
            acc[1][j][2] = fmaf(wa.z, xv.y, acc[1][j][2]);
            acc[1][j][3] = fmaf(wa.w, xv.y, acc[1][j][3]);
        }
        if (P == 0) {
            const float4 wb = *(const float4*)(ws + (ci * 3 + 2) * 64 + co_base);
#pragma unroll
            for (int j = 0; j < JN; ++j) {
                float2 xv = xs2[ci * 13 + i4b[j]];
                acc[0][j][0] = fmaf(wb.x, xv.x, acc[0][j][0]);
                acc[0][j][1] = fmaf(wb.y, xv.x, acc[0][j][1]);
                acc[0][j][2] = fmaf(wb.z, xv.x, acc[0][j][2]);
                acc[0][j][3] = fmaf(wb.w, xv.x, acc[0][j][3]);
                acc[1][j][0] = fmaf(wb.x, xv.y, acc[1][j][0]);
                acc[1][j][1] = fmaf(wb.y, xv.y, acc[1][j][1]);
                acc[1][j][2] = fmaf(wb.z, xv.y, acc[1][j][2]);
                acc[1][j][3] = fmaf(wb.w, xv.y, acc[1][j][3]);
            }
        }
    }
}

__global__ void __launch_bounds__(128, 4)
convt4d_kernel(const float* __restrict__ x,
               const float* __restrict__ bias,
               float* __restrict__ out) {
    extern __shared__ float smem[];
    float* ws  = smem;                 // 12288 floats: [ci][k4][co]
    float* xsf = smem + WSLICE;        // 64*13*2 floats: [ci][i4(0..12)][s], i4=12 is zero pad
    const float2* xs2 = (const float2*)xsf;

    const int bid = blockIdx.x;
    const int tid = threadIdx.x;

    int o3g = bid % 13;
    int r   = bid / 13;
    const int o2 = r % 25; r /= 25;
    const int o1 = r % 25;
    const int b  = r / 25;

    // tap lists dims 1,2
    int n1, k1l[2], i1l[2]; taps(o1, n1, k1l, i1l);
    int n2, k2l[2], i2l[2]; taps(o2, n2, k2l, i2l);

    // o3 same-parity pair
    int o3a, o3b; bool bvalid;
    if (o3g < 7) { o3a = 4 * o3g;        o3b = o3a + 2; bvalid = (o3b <= 24); }
    else         { o3a = 4 * (o3g - 7) + 1; o3b = o3a + 2; bvalid = true; }

    int n3, k3l[2], i3l[2][2];
    if (o3a & 1) {
        n3 = 1; k3l[0] = 1;
        i3l[0][0] = (o3a - 1) >> 1;
        i3l[0][1] = bvalid ? ((o3b - 1) >> 1) : -1;
    } else {
        n3 = 0;
        { int ia = o3a >> 1; int ib = bvalid ? (o3b >> 1) : LI;
          if (ia < LI || ib < LI) {
              k3l[n3] = 0;
              i3l[n3][0] = (ia < LI) ? ia : -1;
              i3l[n3][1] = (bvalid && ib < LI) ? ib : -1;
              n3++; } }
        { int ia = (o3a >> 1) - 1; int ib = bvalid ? ((o3b >> 1) - 1) : -1;
          if (ia >= 0 || ib >= 0) {
              k3l[n3] = 2;
              i3l[n3][0] = (ia >= 0) ? ia : -1;
              i3l[n3][1] = (bvalid && ib >= 0) ? ib : -1;
              n3++; } }
    }

    // thread mapping: parity-pure warps, wave-swizzled for SMSP balance
    const int wrp = tid >> 5, lane = tid & 31;
    const int psw = (bid / 148) & 1;
    const int p   = (wrp & 1) ^ psw;            // o4 parity this warp owns
    const int cl  = (wrp >> 1) * 8 + (lane >> 2);  // [0,16)
    const int m   = lane & 3;                      // [0,4)
    const int co_base = cl * 4;

    int i4a[4], i4b[4], o4v[4];
#pragma unroll
    for (int j = 0; j < 4; ++j) {
        int t = m + 4 * j;
        o4v[j] = 2 * t + p;
        if (p == 0) {
            i4a[j] = (t < LI) ? t : LI;                     // k4=0
            i4b[j] = (t >= 1 && t <= LI) ? (t - 1) : LI;    // k4=2
        } else {
            i4a[j] = (t < LI) ? t : LI;                     // k4=1
            i4b[j] = LI;
        }
    }

    float acc[2][4][4];
#pragma unroll
    for (int s = 0; s < 2; ++s)
#pragma unroll
        for (int j = 0; j < 4; ++j)
#pragma unroll
            for (int c = 0; c < 4; ++c) acc[s][j][c] = 0.f;

    // zero-fill the i4=12 pad slots once (staging never writes them)
    { int ci = tid >> 1, s = tid & 1; xsf[(ci * 13 + 12) * 2 + s] = 0.f; }

    for (int t3 = 0; t3 < n3; ++t3)
    for (int t2 = 0; t2 < n2; ++t2)
    for (int t1 = 0; t1 < n1; ++t1) {
        const int k123 = (k1l[t1] * 3 + k2l[t2]) * 3 + k3l[t3];
        __syncthreads();   // previous compute done before restage

        // stage weights: contiguous float4 copy from pre-transposed scratch
        {
            const float4* gw = (const float4*)(g_wt + (size_t)k123 * WSLICE);
            float4* sw = (float4*)ws;
#pragma unroll 6
            for (int idx = tid; idx < WSLICE / 4; idx += 128) sw[idx] = gw[idx];
        }
        // stage inputs: [ci][i4][s]
        {
            const int i1v = i1l[t1], i2v = i2l[t2];
            const int i30 = i3l[t3][0], i31 = i3l[t3][1];
            const int xoff12 = i1v * 1728 + i2v * 144;
#pragma unroll
            for (int idx = tid; idx < 384; idx += 128) {
                int v  = idx % 3;
                int s  = (idx / 3) & 1;
                int ci = idx / 6;
                int i3 = s ? i31 : i30;
                float4 val = make_float4(0.f, 0.f, 0.f, 0.f);
                if (i3 >= 0)
                    val = *(const float4*)(x + (size_t)(b * 64 + ci) * XCI
                                             + xoff12 + i3 * 12 + v * 4);
                float* dst = xsf + (ci * 13 + v * 4) * 2 + s;
                dst[0] = val.x; dst[2] = val.y; dst[4] = val.z; dst[6] = val.w;
            }
        }
        __syncthreads();

        if (p == 0) inner_loop<0, 4>(ws, xs2, co_base, i4a, i4b, acc);
        else        inner_loop<1, 3>(ws, xs2, co_base, i4a, i4b, acc);
    }

    // epilogue: + bias, streaming stores
    const float4 bv = *(const float4*)(bias + co_base);
    const float bb[4] = {bv.x, bv.y, bv.z, bv.w};
    const int Jn = (p == 0) ? 4 : 3;
#pragma unroll
    for (int s = 0; s < 2; ++s) {
        if (s == 1 && !bvalid) break;
        const int o3 = s ? o3b : o3a;
        const size_t base0 =
            ((((size_t)(b * 64 + co_base) * 25 + o1) * 25 + o2) * 25 + o3) * 25;
        for (int j = 0; j < Jn; ++j) {
            if (o4v[j] > 24) continue;
            const size_t base = base0 + o4v[j];
#pragma unroll
            for (int c = 0; c < 4; ++c)
                __stcs(out + base + (size_t)c * OSTR_C, acc[s][j][c] + bb[c]);
        }
    }
}

extern "C" void kernel_launch(void* const* d_in, const int* in_sizes, int n_in,
                              void* d_out, int out_size) {
    const float* x    = (const float*)d_in[0];
    const float* wgt  = (const float*)d_in[1];
    const float* bias = (const float*)d_in[2];
    float* out        = (float*)d_out;

    // weight pre-transpose (reads 1.3MB; ~microseconds)
    wtrans_kernel<<<(27 * WSLICE + 255) / 256, 256>>>(wgt);

    const int smem_bytes = (WSLICE + 64 * 13 * 2) * sizeof(float);  // 55808
    cudaFuncSetAttribute(convt4d_kernel,
                         cudaFuncAttributeMaxDynamicSharedMemorySize, smem_bytes);

    const int nblocks = 4 * 25 * 25 * 13;  // (b, o1, o2, o3-pair-group)
    convt4d_kernel<<<nblocks, 128, smem_bytes>>>(x, bias, out);
}